// round 8
// baseline (speedup 1.0000x reference)
#include <cuda_runtime.h>
#include <math.h>
#include <stdint.h>

typedef unsigned long long ull;

// ---------------- problem constants ----------------
#define T_DIM 64
#define B_DIM 32
#define C_DIM 256
#define V_DIM 25
#define H_DIM 8
#define HD_DIM 32
#define PLANE  (B_DIM * C_DIM * V_DIM)    // 204800
#define TOT    (T_DIM * PLANE)            // 13107200
#define NF     (T_DIM * B_DIM * V_DIM)    // 51200  (GEMM N)

// ---------------- device scratch ----------------
// GEMM-adjacent layout: [c][t][b][v]  (addr = c*NF + t*800 + b*25 + v)
__device__ __align__(16) float g_qt[TOT];    // qkv_in transposed; later attn
__device__ __align__(16) float g_yq[TOT];    // q bn-conv out; later proj bn-conv out
__device__ __align__(16) float g_yk[TOT];
__device__ __align__(16) float g_yv[TOT];
__device__ __align__(16) float g_qs[TOT];    // q spikes
__device__ __align__(16) float g_kvl[TOT];   // k_s * v_s

__device__ float g_scale[4][C_DIM];
__device__ float g_shift[4][C_DIM];
__device__ float g_topo[H_DIM][V_DIM * V_DIM];
__device__ float g_decay[C_DIM];

// ---------------- helpers ----------------
__device__ __forceinline__ void split_tf32(float x, uint32_t& h, uint32_t& l) {
    asm("cvt.rna.tf32.f32 %0, %1;" : "=r"(h) : "f"(x));
    float lf = x - __uint_as_float(h);
    asm("cvt.rna.tf32.f32 %0, %1;" : "=r"(l) : "f"(lf));
}
__device__ __forceinline__ void mma8(float* c, float4 a, float2 b) {
    asm volatile(
        "mma.sync.aligned.m16n8k8.row.col.f32.tf32.tf32.f32 "
        "{%0,%1,%2,%3}, {%4,%5,%6,%7}, {%8,%9}, {%0,%1,%2,%3};"
        : "+f"(c[0]), "+f"(c[1]), "+f"(c[2]), "+f"(c[3])
        : "r"(__float_as_uint(a.x)), "r"(__float_as_uint(a.y)),
          "r"(__float_as_uint(a.z)), "r"(__float_as_uint(a.w)),
          "r"(__float_as_uint(b.x)), "r"(__float_as_uint(b.y)));
}

// ---------------- K0: prep ----------------
struct PrepArgs {
    const float* w[4];
    const float* gamma[4];
    const float* beta[4];
    const float* mean[4];
    const float* var[4];
    const float* projb;
    const float* base;
    const float* learned;
    const float* sdw;
};

__global__ void k_prep(PrepArgs p) {
    int blk = blockIdx.x, tid = threadIdx.x;
    if (blk < 4) {
        float sc = p.gamma[blk][tid] * rsqrtf(p.var[blk][tid] + 1e-5f);
        float sh = p.beta[blk][tid] - p.mean[blk][tid] * sc;
        if (blk == 3) sh += p.projb[tid] * sc;
        g_scale[blk][tid] = sc;
        g_shift[blk][tid] = sh;
    } else if (blk == 4) {
        if (tid < H_DIM * V_DIM) {
            int h = tid / V_DIM, i = tid - h * V_DIM;
            float l[V_DIM];
            float mx = -1e30f;
            for (int j = 0; j < V_DIM; j++) {
                l[j] = p.base[i * V_DIM + j] + 0.5f * p.learned[(h * V_DIM + i) * V_DIM + j];
                mx = fmaxf(mx, l[j]);
            }
            float sum = 0.f;
            for (int j = 0; j < V_DIM; j++) { l[j] = expf(l[j] - mx); sum += l[j]; }
            float inv = 1.f / sum;
            for (int j = 0; j < V_DIM; j++) g_topo[h][i * V_DIM + j] = l[j] * inv;
        }
    } else {
        float w = p.sdw[tid];
        float sg = 1.f / (1.f + expf(-w));
        g_decay[tid] = fminf(0.99f, fmaxf(0.01f, sg));
    }
}

// ---------------- K1: transpose + qkv_in (qt only) ----------------
__global__ void k_trans(const float* __restrict__ x, const float* __restrict__ alpha) {
    __shared__ float alp[C_DIM];
    int tid = threadIdx.x;
    alp[tid] = alpha[tid];
    __syncthreads();

    int t = blockIdx.x >> 5;
    int b = blockIdx.x & 31;
    const float* xin = x + (size_t)t * PLANE + b * (C_DIM * V_DIM);
    const float* xpr = xin - PLANE;
    int nbase = t * 800 + b * V_DIM;

    for (int idx = tid; idx < C_DIM * V_DIM; idx += 256) {
        int c = idx / V_DIM;
        int v = idx - c * V_DIM;
        float xv = xin[idx];
        float g = (t == 0) ? 0.f : fabsf(xv - xpr[idx]);
        float a = alp[c];
        g_qt[c * NF + nbase + v] = a * g + (1.f - a) * xv;
    }
}

// ---------------- K2/K5: tf32x3 mma.sync GEMM + fused BN ----------------
// Block tile 128x64, BK=16, 256 threads (8 warps), warp tile 64x16. 2 CTA/SM.
#define BM 128
#define BN 64
#define BK 16
#define GTHREADS 256
// float offsets inside one buffer (6144 floats = 24 KB)
#define AH_OFF 0
#define AL_OFF 2048
#define BH_OFF 4096
#define BL_OFF 5120
#define BUF_FLOATS 6144
#define GSMEM_BYTES (2 * BUF_FLOATS * 4)

struct GemmArgs { const float* w0; const float* w1; const float* w2; const float* w3; const float* x; };

__device__ __forceinline__ void stage_load(const float* __restrict__ A, const float* __restrict__ Bptr,
                                           const size_t* Bbase, const int* koff, int strideK,
                                           int kc, int m0, int tid, float* ra, float* rb) {
    int k0 = kc * BK;
#pragma unroll
    for (int i = 0; i < 2; i++) {   // A: two fragment-lane slots per thread
        int fl = tid + i * GTHREADS;
        int lane = fl & 31, rest = fl >> 5;   // rest 0..15: mf 0..7, kf 0..1
        int mf = rest & 7, kf = rest >> 3;
        int g = lane >> 2, c = lane & 3;
        const float* ap = A + (size_t)(m0 + mf * 16 + g) * C_DIM + k0 + kf * 8 + c;
        ra[i * 4 + 0] = ap[0];
        ra[i * 4 + 1] = ap[8 * C_DIM];
        ra[i * 4 + 2] = ap[4];
        ra[i * 4 + 3] = ap[8 * C_DIM + 4];
    }
#pragma unroll
    for (int i = 0; i < 2; i++) {   // B: two fragment-lane slots per thread
        const float* bp = Bptr + Bbase[i] + (size_t)(k0 + koff[i]) * strideK;
        rb[i * 2 + 0] = bp[0];
        rb[i * 2 + 1] = bp[4 * strideK];
    }
}

__device__ __forceinline__ void stage_store(float* sb, int tid, const float* ra, const float* rb) {
#pragma unroll
    for (int i = 0; i < 2; i++) {   // A
        int fl = tid + i * GTHREADS;
        int lane = fl & 31, rest = fl >> 5;
        uint32_t h[4], l[4];
#pragma unroll
        for (int j = 0; j < 4; j++) split_tf32(ra[i * 4 + j], h[j], l[j]);
        int fi = (rest * 32 + lane) * 4;
        *reinterpret_cast<float4*>(sb + AH_OFF + fi) =
            make_float4(__uint_as_float(h[0]), __uint_as_float(h[1]),
                        __uint_as_float(h[2]), __uint_as_float(h[3]));
        *reinterpret_cast<float4*>(sb + AL_OFF + fi) =
            make_float4(__uint_as_float(l[0]), __uint_as_float(l[1]),
                        __uint_as_float(l[2]), __uint_as_float(l[3]));
    }
#pragma unroll
    for (int i = 0; i < 2; i++) {   // B
        int fl = tid + i * GTHREADS;
        int lane = fl & 31, rest = fl >> 5;
        uint32_t h0, l0, h1, l1;
        split_tf32(rb[i * 2 + 0], h0, l0);
        split_tf32(rb[i * 2 + 1], h1, l1);
        int fi = (rest * 32 + lane) * 2;
        *reinterpret_cast<float2*>(sb + BH_OFF + fi) =
            make_float2(__uint_as_float(h0), __uint_as_float(h1));
        *reinterpret_cast<float2*>(sb + BL_OFF + fi) =
            make_float2(__uint_as_float(l0), __uint_as_float(l1));
    }
}

__global__ void __launch_bounds__(GTHREADS, 2) k_gemm_mma(GemmArgs ga, int pass) {
    extern __shared__ float sm[];
    int mt;
    const float* A;
    const float* Bptr;
    float* out;
    bool direct = false;
    if (pass == 0) {
        mt = blockIdx.z;
        A = (mt == 0) ? ga.w0 : (mt == 1) ? ga.w1 : ga.w2;
        if (mt == 2) { Bptr = ga.x; direct = true; }
        else Bptr = g_qt;
        out = (mt == 0) ? g_yq : (mt == 1) ? g_yk : g_yv;
    } else {
        mt = 3;
        A = ga.w3;
        Bptr = g_qt;
        out = g_yq;
    }
    int m0 = blockIdx.y * BM;
    int n0 = blockIdx.x * BN;
    int tid = threadIdx.x;
    int lane = tid & 31, wid = tid >> 5;
    int wm = wid >> 2;   // 0..1  -> 64 rows
    int wn = wid & 3;    // 0..3  -> 16 cols (2 nf)

    // per-thread B addressing (fixed n per slot; only k varies per chunk)
    size_t Bbase[2];
    int koff[2];
    int strideK = direct ? V_DIM : NF;
#pragma unroll
    for (int i = 0; i < 2; i++) {
        int fl = tid + i * GTHREADS;
        int lane2 = fl & 31, rest = fl >> 5;    // rest 0..15: nf 0..7, kf 0..1
        int nf = rest & 7, kf = rest >> 3;
        int g = lane2 >> 2, c = lane2 & 3;
        koff[i] = kf * 8 + c;
        int n = n0 + nf * 8 + g;
        if (direct) {
            int t = n / 800;
            int r = n - t * 800;
            int b = r / V_DIM;
            int v = r - b * V_DIM;
            Bbase[i] = (size_t)t * PLANE + b * (C_DIM * V_DIM) + v;
        } else {
            Bbase[i] = (size_t)n;
        }
    }

    float acc[4][2][4];
#pragma unroll
    for (int i = 0; i < 4; i++)
#pragma unroll
        for (int j = 0; j < 2; j++)
#pragma unroll
            for (int r = 0; r < 4; r++) acc[i][j][r] = 0.f;

    float ra[8], rb[4];
    stage_load(A, Bptr, Bbase, koff, strideK, 0, m0, tid, ra, rb);
    stage_store(sm, tid, ra, rb);
    __syncthreads();

    for (int kc = 0; kc < C_DIM / BK; kc++) {
        float* sb = sm + (kc & 1) * BUF_FLOATS;
        bool more = (kc + 1 < C_DIM / BK);
        if (more) stage_load(A, Bptr, Bbase, koff, strideK, kc + 1, m0, tid, ra, rb);

#pragma unroll
        for (int kf = 0; kf < 2; kf++) {
            float4 Ah4[4], Al4[4];
#pragma unroll
            for (int i = 0; i < 4; i++) {
                int fi = ((kf * 8 + wm * 4 + i) * 32 + lane) * 4;
                Ah4[i] = *reinterpret_cast<const float4*>(sb + AH_OFF + fi);
                Al4[i] = *reinterpret_cast<const float4*>(sb + AL_OFF + fi);
            }
            float2 Bh2[2], Bl2[2];
#pragma unroll
            for (int j = 0; j < 2; j++) {
                int fi = ((kf * 8 + wn * 2 + j) * 32 + lane) * 2;
                Bh2[j] = *reinterpret_cast<const float2*>(sb + BH_OFF + fi);
                Bl2[j] = *reinterpret_cast<const float2*>(sb + BL_OFF + fi);
            }
#pragma unroll
            for (int i = 0; i < 4; i++)
#pragma unroll
                for (int j = 0; j < 2; j++) {
                    mma8(acc[i][j], Ah4[i], Bh2[j]);
                    mma8(acc[i][j], Ah4[i], Bl2[j]);
                    mma8(acc[i][j], Al4[i], Bh2[j]);
                }
        }
        if (more) stage_store(sm + ((kc + 1) & 1) * BUF_FLOATS, tid, ra, rb);
        __syncthreads();
    }

    // epilogue: fused BN, direct fragment stores
    int g = lane >> 2, c = lane & 3;
#pragma unroll
    for (int i = 0; i < 4; i++) {
        int r0 = m0 + wm * 64 + i * 16 + g;
        int r1 = r0 + 8;
        float sc0 = g_scale[mt][r0], sh0 = g_shift[mt][r0];
        float sc1 = g_scale[mt][r1], sh1 = g_shift[mt][r1];
#pragma unroll
        for (int j = 0; j < 2; j++) {
            int ncol = n0 + (wn * 2 + j) * 8 + c * 2;
            *reinterpret_cast<float2*>(out + (size_t)r0 * NF + ncol) =
                make_float2(acc[i][j][0] * sc0 + sh0, acc[i][j][1] * sc0 + sh0);
            *reinterpret_cast<float2*>(out + (size_t)r1 * NF + ncol) =
                make_float2(acc[i][j][2] * sc1 + sh1, acc[i][j][3] * sc1 + sh1);
        }
    }
}

// ---------------- K3: triple LIF + kv_local ----------------
__global__ void k_lif3() {
    int e = blockIdx.x * 256 + threadIdx.x;
    if (e >= PLANE) return;
    int c = e / 800;
    int nb = e - c * 800;
    int bse = c * NF + nb;
    float vq = 0.f, vk = 0.f, vv = 0.f;
    for (int t = 0; t < T_DIM; t++) {
        int off = bse + t * 800;
        float aq = __ldcs(g_yq + off);
        float ak = __ldcs(g_yk + off);
        float av = __ldcs(g_yv + off);
        float q = vq + (aq - vq) * 0.5f;
        float sq = (q >= 1.f) ? 1.f : 0.f;
        vq = q * (1.f - sq);
        float k = vk + (ak - vk) * 0.5f;
        float sk = (k >= 1.f) ? 1.f : 0.f;
        vk = k * (1.f - sk);
        float v = vv + (av - vv) * 0.5f;
        float sv = (v >= 1.f) ? 1.f : 0.f;
        vv = v * (1.f - sv);
        g_qs[off] = sq;
        g_kvl[off] = sk * sv;
    }
}

// ---------------- K4: topo routing + LIF(0.5) + SSRE ----------------
__global__ void __launch_bounds__(224) k_topo_ssre() {
    int bid = blockIdx.x;
    int b = bid >> 5;
    int rest = bid & 31;
    int h = rest >> 2;
    int dg = rest & 3;
    int tid = threadIdx.x;

    __shared__ float topo_s[V_DIM * V_DIM];
    __shared__ float kvb[2][200];
    for (int i = tid; i < V_DIM * V_DIM; i += 224) topo_s[i] = g_topo[h][i];

    bool active = tid < 200;
    int d_local = tid / V_DIM;
    int i = tid - d_local * V_DIM;
    int c = h * HD_DIM + dg * 8 + d_local;
    int pbase = c * NF + b * V_DIM + i;

    float dec = 0.f;
    if (active) dec = g_decay[h * HD_DIM + dg * 8 + d_local];
    float omd = 1.f - dec;
    float vm = 0.f, S = 0.f;

    if (active) kvb[0][tid] = g_kvl[pbase];

    for (int t = 0; t < T_DIM; t++) {
        __syncthreads();
        int cur = t & 1;
        if (t + 1 < T_DIM && active) kvb[cur ^ 1][tid] = g_kvl[pbase + (t + 1) * 800];
        if (active) {
            const float* kr = &kvb[cur][d_local * V_DIM];
            const float* tr = &topo_s[i * V_DIM];
            float sp = 0.f, sp2 = 0.f;
#pragma unroll
            for (int j = 0; j < 24; j += 2) {
                sp += tr[j] * kr[j];
                sp2 += tr[j + 1] * kr[j + 1];
            }
            sp += tr[24] * kr[24] + sp2;
            vm = vm + (sp - vm) * 0.5f;
            float sk = (vm >= 0.5f) ? 1.f : 0.f;
            vm *= (1.f - sk);
            S = dec * S + omd * sk;
            int off = pbase + t * 800;
            g_qt[off] = g_qs[off] * S;
        }
    }
}

// ---------------- K6: final LIF(0.5) + identity ----------------
__global__ void k_final(const float* __restrict__ x, float* __restrict__ out) {
    int e = blockIdx.x * 256 + threadIdx.x;
    if (e >= PLANE) return;
    int c = e / 800;
    int nb = e - c * 800;
    int b = nb / V_DIM;
    int v = nb - b * V_DIM;
    int ybase = c * NF + nb;
    int xoff = b * (C_DIM * V_DIM) + c * V_DIM + v;
    float vm = 0.f;
    for (int t = 0; t < T_DIM; t++) {
        float y = __ldcs(g_yq + ybase + t * 800);
        float vv = vm + (y - vm) * 0.5f;
        float s = (vv >= 0.5f) ? 1.f : 0.f;
        vm = vv * (1.f - s);
        int xo = t * PLANE + xoff;
        out[xo] = s + x[xo];
    }
}

// ---------------- launch ----------------
extern "C" void kernel_launch(void* const* d_in, const int* in_sizes, int n_in,
                              void* d_out, int out_size) {
    const float* x = (const float*)d_in[0];
    const float* alpha = (const float*)d_in[1];

    PrepArgs p;
    p.w[0] = (const float*)d_in[2];
    p.w[1] = (const float*)d_in[3];
    p.w[2] = (const float*)d_in[4];

    if (in_sizes[5] == 625) {
        p.base    = (const float*)d_in[5];
        p.learned = (const float*)d_in[6];
        p.sdw     = (const float*)d_in[7];
        p.w[3]    = (const float*)d_in[8];
        p.projb   = (const float*)d_in[9];
        for (int m = 0; m < 4; m++) {
            int o = 10 + m * 4;
            p.gamma[m] = (const float*)d_in[o + 0];
            p.beta[m]  = (const float*)d_in[o + 1];
            p.mean[m]  = (const float*)d_in[o + 2];
            p.var[m]   = (const float*)d_in[o + 3];
        }
    } else {
        for (int m = 0; m < 3; m++) {
            int o = 5 + m * 4;
            p.gamma[m] = (const float*)d_in[o + 0];
            p.beta[m]  = (const float*)d_in[o + 1];
            p.mean[m]  = (const float*)d_in[o + 2];
            p.var[m]   = (const float*)d_in[o + 3];
        }
        p.base    = (const float*)d_in[17];
        p.learned = (const float*)d_in[18];
        p.sdw     = (const float*)d_in[19];
        p.w[3]    = (const float*)d_in[20];
        p.projb   = (const float*)d_in[21];
        p.gamma[3] = (const float*)d_in[22];
        p.beta[3]  = (const float*)d_in[23];
        p.mean[3]  = (const float*)d_in[24];
        p.var[3]   = (const float*)d_in[25];
    }

    float* out = (float*)d_out;

    cudaFuncSetAttribute(k_gemm_mma, cudaFuncAttributeMaxDynamicSharedMemorySize, GSMEM_BYTES);

    GemmArgs ga;
    ga.w0 = p.w[0]; ga.w1 = p.w[1]; ga.w2 = p.w[2]; ga.w3 = p.w[3]; ga.x = x;

    k_prep<<<6, 256>>>(p);
    k_trans<<<T_DIM * B_DIM, 256>>>(x, alpha);
    k_gemm_mma<<<dim3(NF / BN, C_DIM / BM, 3), GTHREADS, GSMEM_BYTES>>>(ga, 0);
    k_lif3<<<(PLANE + 255) / 256, 256>>>();
    k_topo_ssre<<<B_DIM * H_DIM * 4, 224>>>();
    k_gemm_mma<<<dim3(NF / BN, C_DIM / BM, 1), GTHREADS, GSMEM_BYTES>>>(ga, 1);
    k_final<<<(PLANE + 255) / 256, 256>>>(x, out);
}

// round 9
// speedup vs baseline: 1.3223x; 1.3223x over previous
#include <cuda_runtime.h>
#include <cuda_fp16.h>
#include <math.h>
#include <stdint.h>

typedef unsigned long long ull;

// ---------------- problem constants ----------------
#define T_DIM 64
#define B_DIM 32
#define C_DIM 256
#define V_DIM 25
#define H_DIM 8
#define HD_DIM 32
#define PLANE  (B_DIM * C_DIM * V_DIM)    // 204800
#define TOT    (T_DIM * PLANE)            // 13107200
#define NF     (T_DIM * B_DIM * V_DIM)    // 51200  (GEMM N)

// ---------------- device scratch ----------------
// GEMM-adjacent layout: [c][t][b][v]  (addr = c*NF + t*800 + b*25 + v)
__device__ __align__(16) float g_qt[TOT];    // qkv_in transposed; later attn
__device__ __align__(16) float g_yq[TOT];    // q bn-conv out; later proj bn-conv out
__device__ __align__(16) float g_yk[TOT];
__device__ __align__(16) float g_yv[TOT];
__device__ __align__(16) float g_qs[TOT];    // q spikes
__device__ __align__(16) float g_kvl[TOT];   // k_s * v_s

__device__ float g_scale[4][C_DIM];
__device__ float g_shift[4][C_DIM];
__device__ float g_topo[H_DIM][V_DIM * V_DIM];
__device__ float g_decay[C_DIM];

// ---------------- helpers ----------------
#define LO_SCALE 1024.0f
#define LO_INV   (1.0f / 1024.0f)

// split pair (a,b) into packed f16x2 hi + scaled-residual lo
__device__ __forceinline__ void split_h2(float a, float b, uint32_t& h, uint32_t& l) {
    __half ha = __float2half_rn(a), hb = __float2half_rn(b);
    float ra = (a - __half2float(ha)) * LO_SCALE;
    float rb = (b - __half2float(hb)) * LO_SCALE;
    __half la = __float2half_rn(ra), lb = __float2half_rn(rb);
    __half2 hh = __halves2half2(ha, hb), ll = __halves2half2(la, lb);
    h = *reinterpret_cast<uint32_t*>(&hh);
    l = *reinterpret_cast<uint32_t*>(&ll);
}

// m16n8k16 f16 mma: acc(4 f32) += A(4x f16x2) x B(2x f16x2)
__device__ __forceinline__ void mma16(float* c, const uint32_t* a, const uint32_t* b) {
    asm volatile(
        "mma.sync.aligned.m16n8k16.row.col.f32.f16.f16.f32 "
        "{%0,%1,%2,%3}, {%4,%5,%6,%7}, {%8,%9}, {%0,%1,%2,%3};"
        : "+f"(c[0]), "+f"(c[1]), "+f"(c[2]), "+f"(c[3])
        : "r"(a[0]), "r"(a[1]), "r"(a[2]), "r"(a[3]), "r"(b[0]), "r"(b[1]));
}

// ---------------- K0: prep ----------------
struct PrepArgs {
    const float* w[4];
    const float* gamma[4];
    const float* beta[4];
    const float* mean[4];
    const float* var[4];
    const float* projb;
    const float* base;
    const float* learned;
    const float* sdw;
};

__global__ void k_prep(PrepArgs p) {
    int blk = blockIdx.x, tid = threadIdx.x;
    if (blk < 4) {
        float sc = p.gamma[blk][tid] * rsqrtf(p.var[blk][tid] + 1e-5f);
        float sh = p.beta[blk][tid] - p.mean[blk][tid] * sc;
        if (blk == 3) sh += p.projb[tid] * sc;
        g_scale[blk][tid] = sc;
        g_shift[blk][tid] = sh;
    } else if (blk == 4) {
        if (tid < H_DIM * V_DIM) {
            int h = tid / V_DIM, i = tid - h * V_DIM;
            float l[V_DIM];
            float mx = -1e30f;
            for (int j = 0; j < V_DIM; j++) {
                l[j] = p.base[i * V_DIM + j] + 0.5f * p.learned[(h * V_DIM + i) * V_DIM + j];
                mx = fmaxf(mx, l[j]);
            }
            float sum = 0.f;
            for (int j = 0; j < V_DIM; j++) { l[j] = expf(l[j] - mx); sum += l[j]; }
            float inv = 1.f / sum;
            for (int j = 0; j < V_DIM; j++) g_topo[h][i * V_DIM + j] = l[j] * inv;
        }
    } else {
        float w = p.sdw[tid];
        float sg = 1.f / (1.f + expf(-w));
        g_decay[tid] = fminf(0.99f, fmaxf(0.01f, sg));
    }
}

// ---------------- K1: transpose + qkv_in (qt only) ----------------
__global__ void k_trans(const float* __restrict__ x, const float* __restrict__ alpha) {
    __shared__ float alp[C_DIM];
    int tid = threadIdx.x;
    alp[tid] = alpha[tid];
    __syncthreads();

    int t = blockIdx.x >> 5;
    int b = blockIdx.x & 31;
    const float* xin = x + (size_t)t * PLANE + b * (C_DIM * V_DIM);
    const float* xpr = xin - PLANE;
    int nbase = t * 800 + b * V_DIM;

    for (int idx = tid; idx < C_DIM * V_DIM; idx += 256) {
        int c = idx / V_DIM;
        int v = idx - c * V_DIM;
        float xv = xin[idx];
        float g = (t == 0) ? 0.f : fabsf(xv - xpr[idx]);
        float a = alp[c];
        g_qt[c * NF + nbase + v] = a * g + (1.f - a) * xv;
    }
}

// ---------------- K2/K5: fp16x3 mma.sync GEMM + fused BN ----------------
// Block tile 128x64, BK=16 (one k16-MMA per chunk), 256 threads (8 warps),
// warp tile 64x16, dual accumulators (Markidis split), 2 CTA/SM.
#define BM 128
#define BN 64
#define BK 16
#define GTHREADS 256
// uint32 word offsets inside one buffer (3072 words = 12 KB)
#define AH_OFF 0
#define AL_OFF 1024
#define BH_OFF 2048
#define BL_OFF 2560
#define BUF_WORDS 3072
#define GSMEM_BYTES (2 * BUF_WORDS * 4)

struct GemmArgs { const float* w0; const float* w1; const float* w2; const float* w3; const float* x; };

__device__ __forceinline__ void stage_load(const float* __restrict__ A, const float* __restrict__ Bptr,
                                           size_t Bbase, int bk, int strideK,
                                           int kc, int m0, int tid, float* ra, float* rb) {
    int k0 = kc * BK;
    {   // A: slot = tid; frag mf = tid>>5, lane = tid&31
        int lane = tid & 31, mf = tid >> 5;
        int g = lane >> 2, c = lane & 3;
        const float* ap = A + (size_t)(m0 + mf * 16 + g) * C_DIM + k0 + 2 * c;
        float2 p0 = *reinterpret_cast<const float2*>(ap);
        float2 p1 = *reinterpret_cast<const float2*>(ap + 8);
        float2 q0 = *reinterpret_cast<const float2*>(ap + 8 * C_DIM);
        float2 q1 = *reinterpret_cast<const float2*>(ap + 8 * C_DIM + 8);
        ra[0] = p0.x; ra[1] = p0.y;   // a0: row g,   k 2c..2c+1
        ra[2] = q0.x; ra[3] = q0.y;   // a1: row g+8, k 2c..2c+1
        ra[4] = p1.x; ra[5] = p1.y;   // a2: row g,   k 2c+8..2c+9
        ra[6] = q1.x; ra[7] = q1.y;   // a3: row g+8, k 2c+8..2c+9
    }
    {   // B: slot = tid; frag nf = tid>>5, lane
        const float* bp = Bptr + Bbase + (size_t)(k0 + bk) * strideK;
        rb[0] = bp[0];
        rb[1] = bp[strideK];
        rb[2] = bp[8 * strideK];
        rb[3] = bp[9 * strideK];
    }
}

__device__ __forceinline__ void stage_store(uint32_t* sb, int tid, const float* ra, const float* rb) {
    uint32_t h[4], l[4];
    split_h2(ra[0], ra[1], h[0], l[0]);
    split_h2(ra[2], ra[3], h[1], l[1]);
    split_h2(ra[4], ra[5], h[2], l[2]);
    split_h2(ra[6], ra[7], h[3], l[3]);
    *reinterpret_cast<uint4*>(sb + AH_OFF + tid * 4) = make_uint4(h[0], h[1], h[2], h[3]);
    *reinterpret_cast<uint4*>(sb + AL_OFF + tid * 4) = make_uint4(l[0], l[1], l[2], l[3]);

    uint32_t bh0, bl0, bh1, bl1;
    split_h2(rb[0], rb[1], bh0, bl0);
    split_h2(rb[2], rb[3], bh1, bl1);
    *reinterpret_cast<uint2*>(sb + BH_OFF + tid * 2) = make_uint2(bh0, bh1);
    *reinterpret_cast<uint2*>(sb + BL_OFF + tid * 2) = make_uint2(bl0, bl1);
}

__global__ void __launch_bounds__(GTHREADS, 2) k_gemm_mma(GemmArgs ga, int pass) {
    extern __shared__ uint32_t sm32[];
    int mt;
    const float* A;
    const float* Bptr;
    float* out;
    bool direct = false;
    if (pass == 0) {
        mt = blockIdx.z;
        A = (mt == 0) ? ga.w0 : (mt == 1) ? ga.w1 : ga.w2;
        if (mt == 2) { Bptr = ga.x; direct = true; }
        else Bptr = g_qt;
        out = (mt == 0) ? g_yq : (mt == 1) ? g_yk : g_yv;
    } else {
        mt = 3;
        A = ga.w3;
        Bptr = g_qt;
        out = g_yq;
    }
    int m0 = blockIdx.y * BM;
    int n0 = blockIdx.x * BN;
    int tid = threadIdx.x;
    int lane = tid & 31, wid = tid >> 5;
    int wm = wid >> 2;   // 0..1 -> 64 rows
    int wn = wid & 3;    // 0..3 -> 16 cols (2 nf)

    // per-thread B addressing: slot nf/g fixed; k varies per chunk
    size_t Bbase;
    int bk;
    int strideK = direct ? V_DIM : NF;
    {
        int lane2 = tid & 31, nf = tid >> 5;
        int g = lane2 >> 2, c = lane2 & 3;
        bk = 2 * c;                        // k rows 2c,2c+1,2c+8,2c+9
        int n = n0 + nf * 8 + g;
        if (direct) {
            int t = n / 800;
            int r = n - t * 800;
            int b = r / V_DIM;
            int v = r - b * V_DIM;
            Bbase = (size_t)t * PLANE + b * (C_DIM * V_DIM) + v;
        } else {
            Bbase = (size_t)n;
        }
    }

    float acc1[4][2][4], acc2[4][2][4];
#pragma unroll
    for (int i = 0; i < 4; i++)
#pragma unroll
        for (int j = 0; j < 2; j++)
#pragma unroll
            for (int r = 0; r < 4; r++) { acc1[i][j][r] = 0.f; acc2[i][j][r] = 0.f; }

    float ra[8], rb[4];
    stage_load(A, Bptr, Bbase, bk, strideK, 0, m0, tid, ra, rb);
    stage_store(sm32, tid, ra, rb);
    __syncthreads();

    for (int kc = 0; kc < C_DIM / BK; kc++) {
        uint32_t* sb = sm32 + (kc & 1) * BUF_WORDS;
        bool more = (kc + 1 < C_DIM / BK);
        if (more) stage_load(A, Bptr, Bbase, bk, strideK, kc + 1, m0, tid, ra, rb);

        uint32_t Bh[2][2], Bl[2][2];
#pragma unroll
        for (int j = 0; j < 2; j++) {
            int fi = ((wn * 2 + j) * 32 + lane) * 2;
            uint2 bh = *reinterpret_cast<const uint2*>(sb + BH_OFF + fi);
            uint2 bl = *reinterpret_cast<const uint2*>(sb + BL_OFF + fi);
            Bh[j][0] = bh.x; Bh[j][1] = bh.y;
            Bl[j][0] = bl.x; Bl[j][1] = bl.y;
        }
#pragma unroll
        for (int i = 0; i < 4; i++) {
            int fi = ((wm * 4 + i) * 32 + lane) * 4;
            uint4 ah4 = *reinterpret_cast<const uint4*>(sb + AH_OFF + fi);
            uint4 al4 = *reinterpret_cast<const uint4*>(sb + AL_OFF + fi);
            uint32_t Ah[4] = {ah4.x, ah4.y, ah4.z, ah4.w};
            uint32_t Al[4] = {al4.x, al4.y, al4.z, al4.w};
#pragma unroll
            for (int j = 0; j < 2; j++) {
                mma16(acc1[i][j], Ah, Bh[j]);
                mma16(acc2[i][j], Ah, Bl[j]);
                mma16(acc2[i][j], Al, Bh[j]);
            }
        }
        if (more) stage_store(sm32 + ((kc + 1) & 1) * BUF_WORDS, tid, ra, rb);
        __syncthreads();
    }

    // epilogue: combine split accumulators + fused BN, fragment stores
    int g = lane >> 2, c = lane & 3;
#pragma unroll
    for (int i = 0; i < 4; i++) {
        int r0 = m0 + wm * 64 + i * 16 + g;
        int r1 = r0 + 8;
        float sc0 = g_scale[mt][r0], sh0 = g_shift[mt][r0];
        float sc1 = g_scale[mt][r1], sh1 = g_shift[mt][r1];
#pragma unroll
        for (int j = 0; j < 2; j++) {
            int ncol = n0 + (wn * 2 + j) * 8 + c * 2;
            float v0 = acc1[i][j][0] + acc2[i][j][0] * LO_INV;
            float v1 = acc1[i][j][1] + acc2[i][j][1] * LO_INV;
            float v2 = acc1[i][j][2] + acc2[i][j][2] * LO_INV;
            float v3 = acc1[i][j][3] + acc2[i][j][3] * LO_INV;
            *reinterpret_cast<float2*>(out + (size_t)r0 * NF + ncol) =
                make_float2(v0 * sc0 + sh0, v1 * sc0 + sh0);
            *reinterpret_cast<float2*>(out + (size_t)r1 * NF + ncol) =
                make_float2(v2 * sc1 + sh1, v3 * sc1 + sh1);
        }
    }
}

// ---------------- K3: triple LIF + kv_local ----------------
__global__ void k_lif3() {
    int e = blockIdx.x * 256 + threadIdx.x;
    if (e >= PLANE) return;
    int c = e / 800;
    int nb = e - c * 800;
    int bse = c * NF + nb;
    float vq = 0.f, vk = 0.f, vv = 0.f;
    for (int t = 0; t < T_DIM; t++) {
        int off = bse + t * 800;
        float aq = __ldcs(g_yq + off);
        float ak = __ldcs(g_yk + off);
        float av = __ldcs(g_yv + off);
        float q = vq + (aq - vq) * 0.5f;
        float sq = (q >= 1.f) ? 1.f : 0.f;
        vq = q * (1.f - sq);
        float k = vk + (ak - vk) * 0.5f;
        float sk = (k >= 1.f) ? 1.f : 0.f;
        vk = k * (1.f - sk);
        float v = vv + (av - vv) * 0.5f;
        float sv = (v >= 1.f) ? 1.f : 0.f;
        vv = v * (1.f - sv);
        g_qs[off] = sq;
        g_kvl[off] = sk * sv;
    }
}

// ---------------- K4: topo routing + LIF(0.5) + SSRE ----------------
__global__ void __launch_bounds__(224) k_topo_ssre() {
    int bid = blockIdx.x;
    int b = bid >> 5;
    int rest = bid & 31;
    int h = rest >> 2;
    int dg = rest & 3;
    int tid = threadIdx.x;

    __shared__ float topo_s[V_DIM * V_DIM];
    __shared__ float kvb[2][200];
    for (int i = tid; i < V_DIM * V_DIM; i += 224) topo_s[i] = g_topo[h][i];

    bool active = tid < 200;
    int d_local = tid / V_DIM;
    int i = tid - d_local * V_DIM;
    int c = h * HD_DIM + dg * 8 + d_local;
    int pbase = c * NF + b * V_DIM + i;

    float dec = 0.f;
    if (active) dec = g_decay[h * HD_DIM + dg * 8 + d_local];
    float omd = 1.f - dec;
    float vm = 0.f, S = 0.f;

    if (active) kvb[0][tid] = g_kvl[pbase];

    for (int t = 0; t < T_DIM; t++) {
        __syncthreads();
        int cur = t & 1;
        if (t + 1 < T_DIM && active) kvb[cur ^ 1][tid] = g_kvl[pbase + (t + 1) * 800];
        if (active) {
            const float* kr = &kvb[cur][d_local * V_DIM];
            const float* tr = &topo_s[i * V_DIM];
            float sp = 0.f, sp2 = 0.f;
#pragma unroll
            for (int j = 0; j < 24; j += 2) {
                sp += tr[j] * kr[j];
                sp2 += tr[j + 1] * kr[j + 1];
            }
            sp += tr[24] * kr[24] + sp2;
            vm = vm + (sp - vm) * 0.5f;
            float sk = (vm >= 0.5f) ? 1.f : 0.f;
            vm *= (1.f - sk);
            S = dec * S + omd * sk;
            int off = pbase + t * 800;
            g_qt[off] = g_qs[off] * S;
        }
    }
}

// ---------------- K6: final LIF(0.5) + identity ----------------
__global__ void k_final(const float* __restrict__ x, float* __restrict__ out) {
    int e = blockIdx.x * 256 + threadIdx.x;
    if (e >= PLANE) return;
    int c = e / 800;
    int nb = e - c * 800;
    int b = nb / V_DIM;
    int v = nb - b * V_DIM;
    int ybase = c * NF + nb;
    int xoff = b * (C_DIM * V_DIM) + c * V_DIM + v;
    float vm = 0.f;
    for (int t = 0; t < T_DIM; t++) {
        float y = __ldcs(g_yq + ybase + t * 800);
        float vv = vm + (y - vm) * 0.5f;
        float s = (vv >= 0.5f) ? 1.f : 0.f;
        vm = vv * (1.f - s);
        int xo = t * PLANE + xoff;
        out[xo] = s + x[xo];
    }
}

// ---------------- launch ----------------
extern "C" void kernel_launch(void* const* d_in, const int* in_sizes, int n_in,
                              void* d_out, int out_size) {
    const float* x = (const float*)d_in[0];
    const float* alpha = (const float*)d_in[1];

    PrepArgs p;
    p.w[0] = (const float*)d_in[2];
    p.w[1] = (const float*)d_in[3];
    p.w[2] = (const float*)d_in[4];

    if (in_sizes[5] == 625) {
        p.base    = (const float*)d_in[5];
        p.learned = (const float*)d_in[6];
        p.sdw     = (const float*)d_in[7];
        p.w[3]    = (const float*)d_in[8];
        p.projb   = (const float*)d_in[9];
        for (int m = 0; m < 4; m++) {
            int o = 10 + m * 4;
            p.gamma[m] = (const float*)d_in[o + 0];
            p.beta[m]  = (const float*)d_in[o + 1];
            p.mean[m]  = (const float*)d_in[o + 2];
            p.var[m]   = (const float*)d_in[o + 3];
        }
    } else {
        for (int m = 0; m < 3; m++) {
            int o = 5 + m * 4;
            p.gamma[m] = (const float*)d_in[o + 0];
            p.beta[m]  = (const float*)d_in[o + 1];
            p.mean[m]  = (const float*)d_in[o + 2];
            p.var[m]   = (const float*)d_in[o + 3];
        }
        p.base    = (const float*)d_in[17];
        p.learned = (const float*)d_in[18];
        p.sdw     = (const float*)d_in[19];
        p.w[3]    = (const float*)d_in[20];
        p.projb   = (const float*)d_in[21];
        p.gamma[3] = (const float*)d_in[22];
        p.beta[3]  = (const float*)d_in[23];
        p.mean[3]  = (const float*)d_in[24];
        p.var[3]   = (const float*)d_in[25];
    }

    float* out = (float*)d_out;

    cudaFuncSetAttribute(k_gemm_mma, cudaFuncAttributeMaxDynamicSharedMemorySize, GSMEM_BYTES);

    GemmArgs ga;
    ga.w0 = p.w[0]; ga.w1 = p.w[1]; ga.w2 = p.w[2]; ga.w3 = p.w[3]; ga.x = x;

    k_prep<<<6, 256>>>(p);
    k_trans<<<T_DIM * B_DIM, 256>>>(x, alpha);
    k_gemm_mma<<<dim3(NF / BN, C_DIM / BM, 3), GTHREADS, GSMEM_BYTES>>>(ga, 0);
    k_lif3<<<(PLANE + 255) / 256, 256>>>();
    k_topo_ssre<<<B_DIM * H_DIM * 4, 224>>>();
    k_gemm_mma<<<dim3(NF / BN, C_DIM / BM, 1), GTHREADS, GSMEM_BYTES>>>(ga, 1);
    k_final<<<(PLANE + 255) / 256, 256>>>(x, out);
}